// round 1
// baseline (speedup 1.0000x reference)
#include <cuda_runtime.h>
#include <cuda_bf16.h>
#include <cstdint>

// Problem constants (shapes are fixed by the reference)
#define N_NODES 100000
#define D 256           // D_IN == D_OUT == 256

// Scratch for Z = X @ W^T   (100000 x 256 f32 = 102.4 MB)
__device__ float g_Z[(size_t)N_NODES * D];

// ---------------------------------------------------------------------------
// Kernel 1: out[i][j] = b[j]  (bias broadcast init; out is poisoned by harness)
// ---------------------------------------------------------------------------
__global__ void init_bias_kernel(float* __restrict__ out,
                                 const float* __restrict__ b,
                                 int total) {
    int idx = blockIdx.x * blockDim.x + threadIdx.x;
    if (idx < total) {
        out[idx] = b[idx & (D - 1)];
    }
}

// ---------------------------------------------------------------------------
// Kernel 2: Z = X @ W^T
// X: [M, 256] row-major, W: [256, 256] row-major (K contiguous for both).
// Classic 128x128x8 tile, 256 threads, 8x8 microtile per thread.
// ---------------------------------------------------------------------------
#define BM 128
#define BN 128
#define BK 8
#define TM 8
#define TN 8

__global__ __launch_bounds__(256, 2)
void gemm_xwT_kernel(const float* __restrict__ X,
                     const float* __restrict__ W,
                     float* __restrict__ Z,
                     int M) {
    __shared__ float As[BK][BM];
    __shared__ float Bs[BK][BN];

    const int tid = threadIdx.x;
    const int block_m = blockIdx.y * BM;
    const int block_n = blockIdx.x * BN;

    // global-load mapping: 2 threads per row, each loads one float4 (8 floats/row/iter)
    const int lrow = tid >> 1;            // 0..127
    const int lk4  = (tid & 1) * 4;       // 0 or 4

    // compute mapping: 16x16 threads, each owns an 8x8 microtile
    const int ty = tid >> 4;              // 0..15
    const int tx = tid & 15;              // 0..15

    float acc[TM][TN];
#pragma unroll
    for (int i = 0; i < TM; i++)
#pragma unroll
        for (int j = 0; j < TN; j++) acc[i][j] = 0.0f;

    const int K = D;
    for (int k0 = 0; k0 < K; k0 += BK) {
        // A tile (rows of X) -- guard M edge
        const int gm = block_m + lrow;
        float4 av = make_float4(0.f, 0.f, 0.f, 0.f);
        if (gm < M) av = *reinterpret_cast<const float4*>(X + (size_t)gm * K + k0 + lk4);
        As[lk4 + 0][lrow] = av.x;
        As[lk4 + 1][lrow] = av.y;
        As[lk4 + 2][lrow] = av.z;
        As[lk4 + 3][lrow] = av.w;

        // B tile (rows of W == output columns); N = 256 always in range
        const int gn = block_n + lrow;
        float4 bv = *reinterpret_cast<const float4*>(W + (size_t)gn * K + k0 + lk4);
        Bs[lk4 + 0][lrow] = bv.x;
        Bs[lk4 + 1][lrow] = bv.y;
        Bs[lk4 + 2][lrow] = bv.z;
        Bs[lk4 + 3][lrow] = bv.w;

        __syncthreads();

#pragma unroll
        for (int k = 0; k < BK; ++k) {
            float a[TM], bb[TN];
#pragma unroll
            for (int i = 0; i < TM; i++) a[i] = As[k][ty * TM + i];
#pragma unroll
            for (int j = 0; j < TN; j++) bb[j] = Bs[k][tx * TN + j];
#pragma unroll
            for (int i = 0; i < TM; i++)
#pragma unroll
                for (int j = 0; j < TN; j++)
                    acc[i][j] = fmaf(a[i], bb[j], acc[i][j]);
        }
        __syncthreads();
    }

    // store (float4-vectorized along N)
#pragma unroll
    for (int i = 0; i < TM; i++) {
        const int gm = block_m + ty * TM + i;
        if (gm < M) {
            float* dst = Z + (size_t)gm * D + block_n + tx * TN;
            float4 v0 = make_float4(acc[i][0], acc[i][1], acc[i][2], acc[i][3]);
            float4 v1 = make_float4(acc[i][4], acc[i][5], acc[i][6], acc[i][7]);
            *reinterpret_cast<float4*>(dst)     = v0;
            *reinterpret_cast<float4*>(dst + 4) = v1;
        }
    }
}

// ---------------------------------------------------------------------------
// Kernel 3: SpMM scatter.  One warp per edge:
//   out[row[e]] += val[e] * Z[col[e]]    (256 floats, red.global.add.v4.f32)
// ---------------------------------------------------------------------------
__device__ __forceinline__ void red_add_v4(float* addr, float4 v) {
    asm volatile("red.global.add.v4.f32 [%0], {%1, %2, %3, %4};"
                 :: "l"(addr), "f"(v.x), "f"(v.y), "f"(v.z), "f"(v.w)
                 : "memory");
}

__global__ __launch_bounds__(256)
void spmm_scatter_kernel(const int* __restrict__ erow,
                         const int* __restrict__ ecol,
                         const float* __restrict__ eval,
                         const float* __restrict__ Z,
                         float* __restrict__ out,
                         int E) {
    const int warp = (blockIdx.x * blockDim.x + threadIdx.x) >> 5;
    if (warp >= E) return;
    const int lane = threadIdx.x & 31;

    const int   r = __ldg(erow + warp);
    const int   c = __ldg(ecol + warp);
    const float v = __ldg(eval + warp);

    const float4* src = reinterpret_cast<const float4*>(Z + (size_t)c * D);
    float4 a = __ldg(src + lane);
    float4 b = __ldg(src + lane + 32);

    a.x *= v; a.y *= v; a.z *= v; a.w *= v;
    b.x *= v; b.y *= v; b.z *= v; b.w *= v;

    float* dst = out + (size_t)r * D;
    red_add_v4(dst + lane * 4, a);
    red_add_v4(dst + 128 + lane * 4, b);
}

// ---------------------------------------------------------------------------
// Launch
// Inputs (metadata order): X, edge_row, edge_col, edge_val, W, b
// ---------------------------------------------------------------------------
extern "C" void kernel_launch(void* const* d_in, const int* in_sizes, int n_in,
                              void* d_out, int out_size) {
    const float* X    = (const float*)d_in[0];
    const int*   erow = (const int*)  d_in[1];
    const int*   ecol = (const int*)  d_in[2];
    const float* eval = (const float*)d_in[3];
    const float* W    = (const float*)d_in[4];
    const float* b    = (const float*)d_in[5];
    float*       out  = (float*)d_out;

    const int M = in_sizes[0] / D;   // 100000 nodes
    const int E = in_sizes[1];       // 3200000 edges

    float* Z;
    cudaGetSymbolAddress((void**)&Z, g_Z);

    // 1) out = bias broadcast
    {
        int total = M * D;
        init_bias_kernel<<<(total + 511) / 512, 512>>>(out, b, total);
    }

    // 2) Z = X @ W^T
    {
        dim3 grid(D / BN, (M + BM - 1) / BM);   // (2, 782)
        gemm_xwT_kernel<<<grid, 256>>>(X, W, Z, M);
    }

    // 3) out += A @ Z   (atomic scatter, one warp per edge)
    {
        int warps_per_block = 256 / 32;
        int blocks = (E + warps_per_block - 1) / warps_per_block;
        spmm_scatter_kernel<<<blocks, 256>>>(erow, ecol, eval, Z, out, E);
    }
}

// round 3
// speedup vs baseline: 1.6008x; 1.6008x over previous
#include <cuda_runtime.h>
#include <cuda_bf16.h>
#include <cstdint>

#define N_NODES 100000
#define N_EDGES 3200000
#define D 256

// ---------------- scratch (no allocations allowed) ----------------
__device__ float g_Z[(size_t)N_NODES * D];        // Z = X @ W^T   (102.4 MB)
__device__ int   g_rowptr[N_NODES + 1];           // CSR row offsets
__device__ int   g_cursor[N_NODES];               // scatter cursors
__device__ int   g_cols[N_EDGES];                 // row-sorted cols
__device__ float g_vals[N_EDGES];                 // row-sorted vals

// ---------------------------------------------------------------------------
// GEMM: Z = X @ W^T    (128x128x8 SIMT tile, 8x8 microtile)
// ---------------------------------------------------------------------------
#define BM 128
#define BN 128
#define BK 8
#define TM 8
#define TN 8

__global__ __launch_bounds__(256, 2)
void gemm_xwT_kernel(const float* __restrict__ X,
                     const float* __restrict__ W,
                     float* __restrict__ Z,
                     int M) {
    __shared__ float As[BK][BM];
    __shared__ float Bs[BK][BN];

    const int tid = threadIdx.x;
    const int block_m = blockIdx.y * BM;
    const int block_n = blockIdx.x * BN;

    const int lrow = tid >> 1;
    const int lk4  = (tid & 1) * 4;
    const int ty = tid >> 4;
    const int tx = tid & 15;

    float acc[TM][TN];
#pragma unroll
    for (int i = 0; i < TM; i++)
#pragma unroll
        for (int j = 0; j < TN; j++) acc[i][j] = 0.0f;

    const int K = D;
    for (int k0 = 0; k0 < K; k0 += BK) {
        const int gm = block_m + lrow;
        float4 av = make_float4(0.f, 0.f, 0.f, 0.f);
        if (gm < M) av = *reinterpret_cast<const float4*>(X + (size_t)gm * K + k0 + lk4);
        As[lk4 + 0][lrow] = av.x;
        As[lk4 + 1][lrow] = av.y;
        As[lk4 + 2][lrow] = av.z;
        As[lk4 + 3][lrow] = av.w;

        const int gn = block_n + lrow;
        float4 bv = *reinterpret_cast<const float4*>(W + (size_t)gn * K + k0 + lk4);
        Bs[lk4 + 0][lrow] = bv.x;
        Bs[lk4 + 1][lrow] = bv.y;
        Bs[lk4 + 2][lrow] = bv.z;
        Bs[lk4 + 3][lrow] = bv.w;

        __syncthreads();

#pragma unroll
        for (int k = 0; k < BK; ++k) {
            float a[TM], bb[TN];
#pragma unroll
            for (int i = 0; i < TM; i++) a[i] = As[k][ty * TM + i];
#pragma unroll
            for (int j = 0; j < TN; j++) bb[j] = Bs[k][tx * TN + j];
#pragma unroll
            for (int i = 0; i < TM; i++)
#pragma unroll
                for (int j = 0; j < TN; j++)
                    acc[i][j] = fmaf(a[i], bb[j], acc[i][j]);
        }
        __syncthreads();
    }

#pragma unroll
    for (int i = 0; i < TM; i++) {
        const int gm = block_m + ty * TM + i;
        if (gm < M) {
            float* dst = Z + (size_t)gm * D + block_n + tx * TN;
            *reinterpret_cast<float4*>(dst)     = make_float4(acc[i][0], acc[i][1], acc[i][2], acc[i][3]);
            *reinterpret_cast<float4*>(dst + 4) = make_float4(acc[i][4], acc[i][5], acc[i][6], acc[i][7]);
        }
    }
}

// ---------------------------------------------------------------------------
// Binning kernels
// ---------------------------------------------------------------------------
__global__ void zero_counts_kernel(int n) {
    int i = blockIdx.x * blockDim.x + threadIdx.x;
    if (i <= n) {
        g_rowptr[i] = 0;
        if (i < n) g_cursor[i] = 0;
    }
}

__global__ __launch_bounds__(256)
void hist_kernel(const int* __restrict__ erow, int E) {
    int e = blockIdx.x * blockDim.x + threadIdx.x;
    if (e < E) atomicAdd(&g_rowptr[__ldg(erow + e) + 1], 1);  // result unused -> RED
}

// single-block scan: rowptr[i] = sum of counts[0..i-1]; counts live at rowptr[1..n]
__global__ __launch_bounds__(1024)
void scan_kernel(int n) {
    __shared__ int warp_sums[32];
    const int t = threadIdx.x;
    const int chunk = (n + 1023) / 1024;
    const int begin = 1 + t * chunk;
    const int end   = min(begin + chunk, n + 1);

    int s = 0;
    for (int i = begin; i < end; i++) s += g_rowptr[i];

    // inclusive scan of s across 1024 threads
    const int lane = t & 31, wid = t >> 5;
    int v = s;
#pragma unroll
    for (int o = 1; o < 32; o <<= 1) {
        int u = __shfl_up_sync(0xFFFFFFFFu, v, o);
        if (lane >= o) v += u;
    }
    if (lane == 31) warp_sums[wid] = v;
    __syncthreads();
    if (wid == 0) {
        int w = warp_sums[lane];
#pragma unroll
        for (int o = 1; o < 32; o <<= 1) {
            int u = __shfl_up_sync(0xFFFFFFFFu, w, o);
            if (lane >= o) w += u;
        }
        warp_sums[lane] = w;
    }
    __syncthreads();

    int run = v - s + (wid > 0 ? warp_sums[wid - 1] : 0);   // exclusive prefix
    for (int i = begin; i < end; i++) {
        run += g_rowptr[i];
        g_rowptr[i] = run;
    }
    if (t == 0) g_rowptr[0] = 0;
}

__global__ __launch_bounds__(256)
void scatter_kernel(const int* __restrict__ erow,
                    const int* __restrict__ ecol,
                    const float* __restrict__ eval,
                    int E) {
    int e = blockIdx.x * blockDim.x + threadIdx.x;
    if (e >= E) return;
    const int r = __ldg(erow + e);
    const int pos = g_rowptr[r] + atomicAdd(&g_cursor[r], 1);
    g_cols[pos] = __ldg(ecol + e);
    g_vals[pos] = __ldg(eval + e);
}

// ---------------------------------------------------------------------------
// SpMM: one warp per row, register accumulation, bias fused, single store.
// ---------------------------------------------------------------------------
__global__ __launch_bounds__(256)
void spmm_rows_kernel(const float* __restrict__ Z,
                      const float* __restrict__ b,
                      float* __restrict__ out,
                      int n) {
    const int row = (blockIdx.x * blockDim.x + threadIdx.x) >> 5;
    if (row >= n) return;
    const int lane = threadIdx.x & 31;

    const float4* b4 = reinterpret_cast<const float4*>(b);
    float4 acc0 = __ldg(b4 + lane);
    float4 acc1 = __ldg(b4 + lane + 32);

    const int s = __ldg(g_rowptr + row);
    const int e = __ldg(g_rowptr + row + 1);

    int i = s;
    for (; i + 1 < e; i += 2) {
        const int   c0 = __ldg(g_cols + i);
        const int   c1 = __ldg(g_cols + i + 1);
        const float v0 = __ldg(g_vals + i);
        const float v1 = __ldg(g_vals + i + 1);
        const float4* z0 = reinterpret_cast<const float4*>(Z + (size_t)c0 * D);
        const float4* z1 = reinterpret_cast<const float4*>(Z + (size_t)c1 * D);
        float4 a0 = __ldg(z0 + lane);
        float4 a1 = __ldg(z0 + lane + 32);
        float4 c0v = __ldg(z1 + lane);
        float4 c1v = __ldg(z1 + lane + 32);

        acc0.x = fmaf(v0, a0.x, acc0.x); acc0.y = fmaf(v0, a0.y, acc0.y);
        acc0.z = fmaf(v0, a0.z, acc0.z); acc0.w = fmaf(v0, a0.w, acc0.w);
        acc1.x = fmaf(v0, a1.x, acc1.x); acc1.y = fmaf(v0, a1.y, acc1.y);
        acc1.z = fmaf(v0, a1.z, acc1.z); acc1.w = fmaf(v0, a1.w, acc1.w);

        acc0.x = fmaf(v1, c0v.x, acc0.x); acc0.y = fmaf(v1, c0v.y, acc0.y);
        acc0.z = fmaf(v1, c0v.z, acc0.z); acc0.w = fmaf(v1, c0v.w, acc0.w);
        acc1.x = fmaf(v1, c1v.x, acc1.x); acc1.y = fmaf(v1, c1v.y, acc1.y);
        acc1.z = fmaf(v1, c1v.z, acc1.z); acc1.w = fmaf(v1, c1v.w, acc1.w);
    }
    if (i < e) {
        const int   c0 = __ldg(g_cols + i);
        const float v0 = __ldg(g_vals + i);
        const float4* z0 = reinterpret_cast<const float4*>(Z + (size_t)c0 * D);
        float4 a0 = __ldg(z0 + lane);
        float4 a1 = __ldg(z0 + lane + 32);
        acc0.x = fmaf(v0, a0.x, acc0.x); acc0.y = fmaf(v0, a0.y, acc0.y);
        acc0.z = fmaf(v0, a0.z, acc0.z); acc0.w = fmaf(v0, a0.w, acc0.w);
        acc1.x = fmaf(v0, a1.x, acc1.x); acc1.y = fmaf(v0, a1.y, acc1.y);
        acc1.z = fmaf(v0, a1.z, acc1.z); acc1.w = fmaf(v0, a1.w, acc1.w);
    }

    float4* o = reinterpret_cast<float4*>(out + (size_t)row * D);
    o[lane]      = acc0;
    o[lane + 32] = acc1;
}

// ---------------------------------------------------------------------------
// Launch.  Inputs: X, edge_row, edge_col, edge_val, W, b
// ---------------------------------------------------------------------------
extern "C" void kernel_launch(void* const* d_in, const int* in_sizes, int n_in,
                              void* d_out, int out_size) {
    const float* X    = (const float*)d_in[0];
    const int*   erow = (const int*)  d_in[1];
    const int*   ecol = (const int*)  d_in[2];
    const float* eval = (const float*)d_in[3];
    const float* W    = (const float*)d_in[4];
    const float* b    = (const float*)d_in[5];
    float*       out  = (float*)d_out;

    const int M = in_sizes[0] / D;   // nodes
    const int E = in_sizes[1];       // edges

    float* Z;
    cudaGetSymbolAddress((void**)&Z, g_Z);

    // GEMM first
    {
        dim3 grid(D / BN, (M + BM - 1) / BM);
        gemm_xwT_kernel<<<grid, 256>>>(X, W, Z, M);
    }

    // CSR binning
    zero_counts_kernel<<<(M + 512) / 512, 512>>>(M);
    hist_kernel<<<(E + 255) / 256, 256>>>(erow, E);
    scan_kernel<<<1, 1024>>>(M);
    scatter_kernel<<<(E + 255) / 256, 256>>>(erow, ecol, eval, E);

    // SpMM: one warp per row, bias fused
    {
        const int warps_per_block = 256 / 32;
        const int blocks = (M + warps_per_block - 1) / warps_per_block;
        spmm_rows_kernel<<<blocks, 256>>>(Z, b, out, M);
    }
}

// round 5
// speedup vs baseline: 1.8471x; 1.1539x over previous
#include <cuda_runtime.h>
#include <cuda_bf16.h>
#include <cstdint>

#define N_NODES 100000
#define N_EDGES 3200000
#define D 256

#define SCAN_BLK 1024
#define MAX_SCAN_BLOCKS 1024   // supports up to 1M rows

// ---------------- scratch (no allocations allowed) ----------------
__device__ float g_Z[(size_t)N_NODES * D];        // Z = X @ W^T   (102.4 MB)
__device__ int   g_rowptr[N_NODES + 1];           // CSR row offsets
__device__ int   g_cursor[N_NODES];               // scatter cursors
__device__ int2  g_edges[N_EDGES];                // row-sorted (col, val-bits)
__device__ int   g_blocksums[MAX_SCAN_BLOCKS];    // scan partials

// ---------------------------------------------------------------------------
// GEMM: Z = X @ W^T    (128x128x8 SIMT tile, 8x8 microtile)
// ---------------------------------------------------------------------------
#define BM 128
#define BN 128
#define BK 8
#define TM 8
#define TN 8

__global__ __launch_bounds__(256, 2)
void gemm_xwT_kernel(const float* __restrict__ X,
                     const float* __restrict__ W,
                     float* __restrict__ Z,
                     int M) {
    __shared__ float As[BK][BM];
    __shared__ float Bs[BK][BN];

    const int tid = threadIdx.x;
    const int block_m = blockIdx.y * BM;
    const int block_n = blockIdx.x * BN;

    const int lrow = tid >> 1;
    const int lk4  = (tid & 1) * 4;
    const int ty = tid >> 4;
    const int tx = tid & 15;

    float acc[TM][TN];
#pragma unroll
    for (int i = 0; i < TM; i++)
#pragma unroll
        for (int j = 0; j < TN; j++) acc[i][j] = 0.0f;

    const int K = D;
    for (int k0 = 0; k0 < K; k0 += BK) {
        const int gm = block_m + lrow;
        float4 av = make_float4(0.f, 0.f, 0.f, 0.f);
        if (gm < M) av = *reinterpret_cast<const float4*>(X + (size_t)gm * K + k0 + lk4);
        As[lk4 + 0][lrow] = av.x;
        As[lk4 + 1][lrow] = av.y;
        As[lk4 + 2][lrow] = av.z;
        As[lk4 + 3][lrow] = av.w;

        const int gn = block_n + lrow;
        float4 bv = *reinterpret_cast<const float4*>(W + (size_t)gn * K + k0 + lk4);
        Bs[lk4 + 0][lrow] = bv.x;
        Bs[lk4 + 1][lrow] = bv.y;
        Bs[lk4 + 2][lrow] = bv.z;
        Bs[lk4 + 3][lrow] = bv.w;

        __syncthreads();

#pragma unroll
        for (int k = 0; k < BK; ++k) {
            float a[TM], bb[TN];
#pragma unroll
            for (int i = 0; i < TM; i++) a[i] = As[k][ty * TM + i];
#pragma unroll
            for (int j = 0; j < TN; j++) bb[j] = Bs[k][tx * TN + j];
#pragma unroll
            for (int i = 0; i < TM; i++)
#pragma unroll
                for (int j = 0; j < TN; j++)
                    acc[i][j] = fmaf(a[i], bb[j], acc[i][j]);
        }
        __syncthreads();
    }

#pragma unroll
    for (int i = 0; i < TM; i++) {
        const int gm = block_m + ty * TM + i;
        if (gm < M) {
            float* dst = Z + (size_t)gm * D + block_n + tx * TN;
            *reinterpret_cast<float4*>(dst)     = make_float4(acc[i][0], acc[i][1], acc[i][2], acc[i][3]);
            *reinterpret_cast<float4*>(dst + 4) = make_float4(acc[i][4], acc[i][5], acc[i][6], acc[i][7]);
        }
    }
}

// ---------------------------------------------------------------------------
// Binning
// ---------------------------------------------------------------------------
__global__ void zero_counts_kernel(int n) {
    int i = blockIdx.x * blockDim.x + threadIdx.x;
    if (i <= n) {
        g_rowptr[i] = 0;
        if (i < n) g_cursor[i] = 0;
    }
}

__global__ __launch_bounds__(256)
void hist_kernel(const int* __restrict__ erow, int E) {
    int e = blockIdx.x * blockDim.x + threadIdx.x;
    if (e < E) atomicAdd(&g_rowptr[__ldg(erow + e) + 1], 1);  // result unused -> RED
}

// ---- multi-block exclusive scan of counts (counts live at rowptr[1..n]) ----

// phase 1: per-block sums
__global__ __launch_bounds__(SCAN_BLK)
void scan_partial_kernel(int n) {
    __shared__ int wsum[32];
    const int i = blockIdx.x * SCAN_BLK + threadIdx.x;
    int v = (i < n) ? g_rowptr[1 + i] : 0;

    const int lane = threadIdx.x & 31, wid = threadIdx.x >> 5;
#pragma unroll
    for (int o = 16; o > 0; o >>= 1) v += __shfl_down_sync(0xFFFFFFFFu, v, o);
    if (lane == 0) wsum[wid] = v;
    __syncthreads();
    if (wid == 0) {
        int w = (lane < SCAN_BLK / 32) ? wsum[lane] : 0;
#pragma unroll
        for (int o = 16; o > 0; o >>= 1) w += __shfl_down_sync(0xFFFFFFFFu, w, o);
        if (lane == 0) g_blocksums[blockIdx.x] = w;
    }
}

// phase 2: exclusive scan of block sums (nb <= 1024), single block
__global__ __launch_bounds__(SCAN_BLK)
void scan_blocksums_kernel(int nb) {
    __shared__ int wsum[32];
    const int t = threadIdx.x;
    int v = (t < nb) ? g_blocksums[t] : 0;

    const int lane = t & 31, wid = t >> 5;
    int inc = v;
#pragma unroll
    for (int o = 1; o < 32; o <<= 1) {
        int u = __shfl_up_sync(0xFFFFFFFFu, inc, o);
        if (lane >= o) inc += u;
    }
    if (lane == 31) wsum[wid] = inc;
    __syncthreads();
    if (wid == 0) {
        int w = wsum[lane];
#pragma unroll
        for (int o = 1; o < 32; o <<= 1) {
            int u = __shfl_up_sync(0xFFFFFFFFu, w, o);
            if (lane >= o) w += u;
        }
        wsum[lane] = w;
    }
    __syncthreads();
    int excl = inc - v + (wid > 0 ? wsum[wid - 1] : 0);
    if (t < nb) g_blocksums[t] = excl;
}

// phase 3: block-local exclusive scan + block offset -> rowptr
__global__ __launch_bounds__(SCAN_BLK)
void scan_apply_kernel(int n) {
    __shared__ int wsum[32];
    const int i = blockIdx.x * SCAN_BLK + threadIdx.x;
    int v = (i < n) ? g_rowptr[1 + i] : 0;

    const int lane = threadIdx.x & 31, wid = threadIdx.x >> 5;
    int inc = v;
#pragma unroll
    for (int o = 1; o < 32; o <<= 1) {
        int u = __shfl_up_sync(0xFFFFFFFFu, inc, o);
        if (lane >= o) inc += u;
    }
    if (lane == 31) wsum[wid] = inc;
    __syncthreads();
    if (wid == 0) {
        int w = wsum[lane];
#pragma unroll
        for (int o = 1; o < 32; o <<= 1) {
            int u = __shfl_up_sync(0xFFFFFFFFu, w, o);
            if (lane >= o) w += u;
        }
        wsum[lane] = w;
    }
    __syncthreads();

    const int base = g_blocksums[blockIdx.x];
    // rowptr[1+i] = base + inclusive-scan-within-block  (== exclusive end of row i)
    if (i < n) g_rowptr[1 + i] = base + inc + (wid > 0 ? wsum[wid - 1] : 0);
    if (i == 0) g_rowptr[0] = 0;
}

__global__ __launch_bounds__(256)
void scatter_kernel(const int* __restrict__ erow,
                    const int* __restrict__ ecol,
                    const float* __restrict__ eval,
                    int E) {
    int e = blockIdx.x * blockDim.x + threadIdx.x;
    if (e >= E) return;
    const int r = __ldg(erow + e);
    const int pos = g_rowptr[r] + atomicAdd(&g_cursor[r], 1);
    g_edges[pos] = make_int2(__ldg(ecol + e), __float_as_int(__ldg(eval + e)));
}

// ---------------------------------------------------------------------------
// SpMM: one warp per row, 4-wide edge unroll, bias fused, single store.
// ---------------------------------------------------------------------------
__device__ __forceinline__ void fma8(float4& a0, float4& a1, float v,
                                     const float4* z, int lane) {
    float4 x0 = __ldg(z + lane);
    float4 x1 = __ldg(z + lane + 32);
    a0.x = fmaf(v, x0.x, a0.x); a0.y = fmaf(v, x0.y, a0.y);
    a0.z = fmaf(v, x0.z, a0.z); a0.w = fmaf(v, x0.w, a0.w);
    a1.x = fmaf(v, x1.x, a1.x); a1.y = fmaf(v, x1.y, a1.y);
    a1.z = fmaf(v, x1.z, a1.z); a1.w = fmaf(v, x1.w, a1.w);
}

__global__ __launch_bounds__(256)
void spmm_rows_kernel(const float* __restrict__ Z,
                      const float* __restrict__ b,
                      float* __restrict__ out,
                      int n) {
    const int row = (blockIdx.x * blockDim.x + threadIdx.x) >> 5;
    if (row >= n) return;
    const int lane = threadIdx.x & 31;

    const float4* b4 = reinterpret_cast<const float4*>(b);
    float4 acc0 = __ldg(b4 + lane);
    float4 acc1 = __ldg(b4 + lane + 32);

    const int s = __ldg(g_rowptr + row);
    const int e = __ldg(g_rowptr + row + 1);

    int i = s;
    for (; i + 3 < e; i += 4) {
        const int2 e0 = __ldg(g_edges + i);
        const int2 e1 = __ldg(g_edges + i + 1);
        const int2 e2 = __ldg(g_edges + i + 2);
        const int2 e3 = __ldg(g_edges + i + 3);
        const float4* z0 = reinterpret_cast<const float4*>(Z + (size_t)e0.x * D);
        const float4* z1 = reinterpret_cast<const float4*>(Z + (size_t)e1.x * D);
        const float4* z2 = reinterpret_cast<const float4*>(Z + (size_t)e2.x * D);
        const float4* z3 = reinterpret_cast<const float4*>(Z + (size_t)e3.x * D);
        // issue all 8 gathers, then consume (compiler batches LDGs)
        float4 x00 = __ldg(z0 + lane),      x01 = __ldg(z0 + lane + 32);
        float4 x10 = __ldg(z1 + lane),      x11 = __ldg(z1 + lane + 32);
        float4 x20 = __ldg(z2 + lane),      x21 = __ldg(z2 + lane + 32);
        float4 x30 = __ldg(z3 + lane),      x31 = __ldg(z3 + lane + 32);
        const float v0 = __int_as_float(e0.y), v1 = __int_as_float(e1.y);
        const float v2 = __int_as_float(e2.y), v3 = __int_as_float(e3.y);

        acc0.x = fmaf(v0, x00.x, acc0.x); acc0.y = fmaf(v0, x00.y, acc0.y);
        acc0.z = fmaf(v0, x00.z, acc0.z); acc0.w = fmaf(v0, x00.w, acc0.w);
        acc1.x = fmaf(v0, x01.x, acc1.x); acc1.y = fmaf(v0, x01.y, acc1.y);
        acc1.z = fmaf(v0, x01.z, acc1.z); acc1.w = fmaf(v0, x01.w, acc1.w);

        acc0.x = fmaf(v1, x10.x, acc0.x); acc0.y = fmaf(v1, x10.y, acc0.y);
        acc0.z = fmaf(v1, x10.z, acc0.z); acc0.w = fmaf(v1, x10.w, acc0.w);
        acc1.x = fmaf(v1, x11.x, acc1.x); acc1.y = fmaf(v1, x11.y, acc1.y);
        acc1.z = fmaf(v1, x11.z, acc1.z); acc1.w = fmaf(v1, x11.w, acc1.w);

        acc0.x = fmaf(v2, x20.x, acc0.x); acc0.y = fmaf(v2, x20.y, acc0.y);
        acc0.z = fmaf(v2, x20.z, acc0.z); acc0.w = fmaf(v2, x20.w, acc0.w);
        acc1.x = fmaf(v2, x21.x, acc1.x); acc1.y = fmaf(v2, x21.y, acc1.y);
        acc1.z = fmaf(v2, x21.z, acc1.z); acc1.w = fmaf(v2, x21.w, acc1.w);

        acc0.x = fmaf(v3, x30.x, acc0.x); acc0.y = fmaf(v3, x30.y, acc0.y);
        acc0.z = fmaf(v3, x30.z, acc0.z); acc0.w = fmaf(v3, x30.w, acc0.w);
        acc1.x = fmaf(v3, x31.x, acc1.x); acc1.y = fmaf(v3, x31.y, acc1.y);
        acc1.z = fmaf(v3, x31.z, acc1.z); acc1.w = fmaf(v3, x31.w, acc1.w);
    }
    for (; i < e; i++) {
        const int2 e0 = __ldg(g_edges + i);
        fma8(acc0, acc1, __int_as_float(e0.y),
             reinterpret_cast<const float4*>(Z + (size_t)e0.x * D), lane);
    }

    float4* o = reinterpret_cast<float4*>(out + (size_t)row * D);
    o[lane]      = acc0;
    o[lane + 32] = acc1;
}

// ---------------------------------------------------------------------------
// Launch.  Inputs: X, edge_row, edge_col, edge_val, W, b
// ---------------------------------------------------------------------------
extern "C" void kernel_launch(void* const* d_in, const int* in_sizes, int n_in,
                              void* d_out, int out_size) {
    const float* X    = (const float*)d_in[0];
    const int*   erow = (const int*)  d_in[1];
    const int*   ecol = (const int*)  d_in[2];
    const float* eval = (const float*)d_in[3];
    const float* W    = (const float*)d_in[4];
    const float* b    = (const float*)d_in[5];
    float*       out  = (float*)d_out;

    const int M = in_sizes[0] / D;   // nodes
    const int E = in_sizes[1];       // edges

    float* Z;
    cudaGetSymbolAddress((void**)&Z, g_Z);

    // GEMM
    {
        dim3 grid(D / BN, (M + BM - 1) / BM);
        gemm_xwT_kernel<<<grid, 256>>>(X, W, Z, M);
    }

    // CSR binning
    zero_counts_kernel<<<(M + 512) / 512, 512>>>(M);
    hist_kernel<<<(E + 255) / 256, 256>>>(erow, E);

    const int nb = (M + SCAN_BLK - 1) / SCAN_BLK;   // 98 blocks for 100k rows
    scan_partial_kernel<<<nb, SCAN_BLK>>>(M);
    scan_blocksums_kernel<<<1, SCAN_BLK>>>(nb);
    scan_apply_kernel<<<nb, SCAN_BLK>>>(M);

    scatter_kernel<<<(E + 255) / 256, 256>>>(erow, ecol, eval, E);

    // SpMM: one warp per row, bias fused
    {
        const int warps_per_block = 256 / 32;
        const int blocks = (M + warps_per_block - 1) / warps_per_block;
        spmm_rows_kernel<<<blocks, 256>>>(Z, b, out, M);
    }
}